// round 9
// baseline (speedup 1.0000x reference)
#include <cuda_runtime.h>
#include <math.h>

#define T_STEPS 20
#define NEGV -1e9f
#define FULL 0xffffffffu

__device__ __forceinline__ float tanhapx(float x) {
    float y;
    asm("tanh.approx.f32 %0, %1;" : "=f"(y) : "f"(x));
    return y;
}
__device__ __forceinline__ float sigapx(float x) {
    return fmaf(0.5f, tanhapx(0.5f * x), 0.5f);
}
// monotone float->uint key (total order, incl. negatives)
__device__ __forceinline__ unsigned sortable(float v) {
    unsigned b = __float_as_uint(v);
    return b ^ (unsigned)(((int)b >> 31) | 0x80000000);
}

__global__ __launch_bounds__(128, 1)
void controller_kernel(const float* __restrict__ w_ih,
                       const float* __restrict__ w_hh,
                       const float* __restrict__ b_ih,
                       const float* __restrict__ b_hh,
                       const float* __restrict__ g_emb,
                       const float* __restrict__ emb_kernel,
                       const float* __restrict__ emb_down,
                       const float* __restrict__ emb_up,
                       const float* __restrict__ w_kernel,
                       const float* __restrict__ w_down,
                       const float* __restrict__ w_up,
                       const float* __restrict__ noise,
                       float* __restrict__ out,
                       int out_size) {
    // Wx[e][r] = (w_ih @ emb_e)[r] + b_ih[r] + b_hh[r]
    // e: 0 = g_emb, 1..8 = kernel, 9..11 = down, 12..14 = up
    __shared__ float Wx[15][128];
    __shared__ __align__(16) float embsh[15][32];
    __shared__ __align__(16) float hsh[4][32];     // per-warp private h
    __shared__ __align__(16) float4 act4[2][32];   // [buf][state] = {i,f,g,o}
    __shared__ float gsh[160];                     // gumbels (mask folded in)
    __shared__ __align__(16) float projsh[3][8 * 36];
    __shared__ float logsh[T_STEPS][8];
    __shared__ int   ssh[T_STEPS];

    const int tid = threadIdx.x;
    const int wid = tid >> 5;
    const int j   = tid & 31;
    const int a   = j & 7;
    const int seg = j >> 3;
    const int sb  = seg * 8;
    // transposed act slot for this thread's gate row
    float* const act_w0 = ((float*)act4[0]) + ((tid & 31) * 4 + (tid >> 5));
    float* const act_w1 = ((float*)act4[1]) + ((tid & 31) * 4 + (tid >> 5));

    // ---- load W rows for gate-row `tid` ----
    float wr[32];   // w_hh row (loop)
    float wi[32];   // w_ih row (init only)
    {
        const float4* wi4 = (const float4*)w_ih;
        const float4* wh4 = (const float4*)w_hh;
#pragma unroll
        for (int i = 0; i < 8; ++i) {
            float4 b = wh4[tid * 8 + i];
            wr[4 * i + 0] = b.x; wr[4 * i + 1] = b.y;
            wr[4 * i + 2] = b.z; wr[4 * i + 3] = b.w;
            float4 q = wi4[tid * 8 + i];
            wi[4 * i + 0] = q.x; wi[4 * i + 1] = q.y;
            wi[4 * i + 2] = q.z; wi[4 * i + 3] = q.w;
        }
    }
    const float bias = b_ih[tid] + b_hh[tid];

    // ---- stage embeddings / proj tables / gumbels ----
    for (int i = tid; i < 3 * 8 * 36; i += 128)
        ((float*)projsh)[i] = 0.0f;
    if (tid < 32) embsh[0][tid] = g_emb[tid];
    for (int i = tid; i < 8 * 32; i += 128)
        embsh[1 + (i >> 5)][i & 31] = emb_kernel[i];
    for (int i = tid; i < 3 * 32; i += 128) {
        embsh[9  + (i >> 5)][i & 31] = emb_down[i];
        embsh[12 + (i >> 5)][i & 31] = emb_up[i];
    }
    // gumbels with the class mask folded in: invalid (t>=14, a>=3) -> -3e9
    for (int i = tid; i < T_STEPS * 8; i += 128) {
        const int tt = i >> 3, aa = i & 7;
        const bool valid = (tt < 14) || (aa < 3);
        float u = noise[i];
        gsh[i] = valid ? -logf(-logf(u * (1.0f - 1e-6f) + 1e-7f)) : -3e9f;
    }
    ((float*)hsh)[tid] = 0.0f;
    __syncthreads();

    for (int i = tid; i < 8 * 32; i += 128)
        projsh[0][(i >> 5) * 36 + (i & 31)] = w_kernel[i];
    for (int i = tid; i < 3 * 32; i += 128) {
        projsh[1][(i >> 5) * 36 + (i & 31)] = w_down[i];
        projsh[2][(i >> 5) * 36 + (i & 31)] = w_up[i];
    }

    // ---- precompute Wx (ILP across the 15 matvecs) ----
#pragma unroll 5
    for (int e = 0; e < 15; ++e) {
        const float4* em4 = (const float4*)embsh[e];
        float a0 = bias, a1 = 0.0f, a2 = 0.0f, a3 = 0.0f;
#pragma unroll
        for (int i = 0; i < 8; ++i) {
            float4 v = em4[i];
            a0 = fmaf(wi[4 * i + 0], v.x, a0);
            a1 = fmaf(wi[4 * i + 1], v.y, a1);
            a2 = fmaf(wi[4 * i + 2], v.z, a2);
            a3 = fmaf(wi[4 * i + 3], v.w, a3);
        }
        Wx[e][tid] = (a0 + a1) + (a2 + a3);
    }
    __syncthreads();

    const bool is_sig = (tid < 64) || (tid >= 96);   // warp-uniform

    // phase-0 state: proj regs, candidate Wx prefetch
    float4 p0v, p1v;
    {
        const float* pr = &projsh[0][a * 36 + sb];
        p0v = *(const float4*)(pr);
        p1v = *(const float4*)(pr + 4);
    }
    float w0 = Wx[1][tid], w1 = Wx[2][tid], w2 = Wx[3][tid], w3 = Wx[4][tid];
    float w4 = Wx[5][tid], w5 = Wx[6][tid], w6 = Wx[7][tid], w7 = Wx[8][tid];

    // act for t=0: h0 = 0 -> gacc = Wx[0]
    {
        const float g0 = Wx[0][tid];
        *act_w0 = is_sig ? sigapx(g0) : tanhapx(g0);
    }
    float c = 0.0f;
    float st_logit = 0.0f;           // deferred stash (written after BAR)
    int   st_s = 0;
    __syncthreads();

#pragma unroll 2
    for (int t = 0; t < T_STEPS; ++t) {
        // phase change (logit proj + emb candidates)
        if (t == 14 || t == 17) {
            const int phi = (t == 14) ? 1 : 2;
            const int eb  = (t == 14) ? 9 : 12;
            const float* pr = &projsh[phi][a * 36 + sb];
            p0v = *(const float4*)(pr);
            p1v = *(const float4*)(pr + 4);
            w0 = Wx[eb][tid]; w1 = Wx[eb + 1][tid]; w2 = Wx[eb + 2][tid];
            // w3..w7 stale but unreachable (invalid classes masked via gsh)
        }
        const int tb = t & 1;
        const float gl = gsh[t * 8 + a];

        // ---- LSTM cell: one LDS.128 of transposed activations ----
        const float4 av = act4[tb][j];      // {i, f, g, o} for state j
        c = fmaf(av.y, c, av.x * av.z);
        const float h = av.w * tanhapx(c);

        // ---- stash previous step's stats AFTER its barrier (off-path) ----
        if (t > 0 && tid < 8) {
            logsh[t - 1][a] = st_logit;
            if (tid == 0) ssh[t - 1] = st_s;
        }

        // ---- logits: gather 8 h values via shfl, dot with proj regs ----
        float l0 = p0v.x * __shfl_sync(FULL, h, sb + 0);
        float l1 = p0v.y * __shfl_sync(FULL, h, sb + 1);
        l0 = fmaf(p0v.z, __shfl_sync(FULL, h, sb + 2), l0);
        l1 = fmaf(p0v.w, __shfl_sync(FULL, h, sb + 3), l1);
        l0 = fmaf(p1v.x, __shfl_sync(FULL, h, sb + 4), l0);
        l1 = fmaf(p1v.y, __shfl_sync(FULL, h, sb + 5), l1);
        l0 = fmaf(p1v.z, __shfl_sync(FULL, h, sb + 6), l0);
        l1 = fmaf(p1v.w, __shfl_sync(FULL, h, sb + 7), l1);
        float part = l0 + l1;
        part += __shfl_xor_sync(FULL, part, 8);
        part += __shfl_xor_sync(FULL, part, 16);
        // NOTE: part is the raw logit; invalid classes are masked via gl
        // (gsh = -3e9) for sampling and re-masked in the deferred stats.

        // ---- publish h; next-step w_hh @ h matvec (overlaps argmax) ----
        hsh[wid][j] = h;
        __syncwarp();
        float a0 = 0.0f, a1 = 0.0f, a2 = 0.0f, a3 = 0.0f;
        const float4* h4 = (const float4*)hsh[wid];
#pragma unroll
        for (int i = 0; i < 8; ++i) {
            float4 v = h4[i];
            a0 = fmaf(wr[4 * i + 0], v.x, a0);
            a1 = fmaf(wr[4 * i + 1], v.y, a1);
            a2 = fmaf(wr[4 * i + 2], v.z, a2);
            a3 = fmaf(wr[4 * i + 3], v.w, a3);
        }
        const float ghh = (a0 + a1) + (a2 + a3);

        // ---- Gumbel-argmax: index in key low bits, one redux ----
        const unsigned key = (sortable(part + gl) & ~7u) | (unsigned)(7 - a);
        unsigned km;
        asm("redux.sync.max.u32 %0, %1, 0xffffffff;" : "=r"(km) : "r"(key));
        const int s = 7 - (int)(km & 7u);

        st_logit = part;
        st_s = s;

        // ---- select sampled Wx, single activation (post-select) ----
        if (t < T_STEPS - 1) {
            const float t01 = (s & 1) ? w1 : w0;
            const float t23 = (s & 1) ? w3 : w2;
            const float t45 = (s & 1) ? w5 : w4;
            const float t67 = (s & 1) ? w7 : w6;
            const float t03 = (s & 2) ? t23 : t01;
            const float t47 = (s & 2) ? t67 : t45;
            const float wx  = (s & 4) ? t47 : t03;
            const float gacc = ghh + wx;
            const float actv = is_sig ? sigapx(gacc) : tanhapx(gacc);
            if (tb) *act_w0 = actv; else *act_w1 = actv;
        }
        __syncthreads();
    }

    // final stash
    if (tid < 8) {
        logsh[T_STEPS - 1][a] = st_logit;
        if (tid == 0) ssh[T_STEPS - 1] = st_s;
    }
    __syncthreads();

    // ---- deferred stats: 20 softmaxes in parallel (warp 0) ----
    if (wid == 0) {
        float lp = 0.0f, ent = 0.0f;
        if (j < T_STEPS) {
            const int s = ssh[j];
            const int nvalid = (j < 14) ? 8 : 3;
            float se = 0.0f, ss1 = 0.0f;
#pragma unroll
            for (int k = 0; k < 8; ++k) {
                if (k < nvalid) {
                    const float l = logsh[j][k];
                    const float e = __expf(l);
                    se  += e;
                    ss1 += e * l;
                }
            }
            const float lse = __logf(se);
            lp  = logsh[j][s] - lse;
            ent = lse - __fdividef(ss1, se);
            out[2 + j] = (float)s;
        }
#pragma unroll
        for (int o = 16; o > 0; o >>= 1) {
            lp  += __shfl_xor_sync(FULL, lp,  o);
            ent += __shfl_xor_sync(FULL, ent, o);
        }
        if (j == 0) {
            out[0] = lp;
            out[1] = ent;
        }
    }
}

extern "C" void kernel_launch(void* const* d_in, const int* in_sizes, int n_in,
                              void* d_out, int out_size) {
    const float* w_ih       = (const float*)d_in[0];
    const float* w_hh       = (const float*)d_in[1];
    const float* b_ih       = (const float*)d_in[2];
    const float* b_hh       = (const float*)d_in[3];
    const float* g_emb      = (const float*)d_in[4];
    const float* emb_kernel = (const float*)d_in[5];
    const float* emb_down   = (const float*)d_in[6];
    const float* emb_up     = (const float*)d_in[7];
    const float* w_kernel   = (const float*)d_in[8];
    const float* w_down     = (const float*)d_in[9];
    const float* w_up       = (const float*)d_in[10];
    const float* noise      = (const float*)d_in[11];
    float* out = (float*)d_out;

    controller_kernel<<<1, 128>>>(w_ih, w_hh, b_ih, b_hh, g_emb,
                                  emb_kernel, emb_down, emb_up,
                                  w_kernel, w_down, w_up, noise,
                                  out, out_size);
}

// round 10
// speedup vs baseline: 1.4742x; 1.4742x over previous
#include <cuda_runtime.h>
#include <math.h>

#define T_STEPS 20
#define FULL 0xffffffffu

__device__ __forceinline__ float tanhapx(float x) {
    float y;
    asm("tanh.approx.f32 %0, %1;" : "=f"(y) : "f"(x));
    return y;
}
__device__ __forceinline__ float sigapx(float x) {
    return fmaf(0.5f, tanhapx(0.5f * x), 0.5f);
}
// monotone float->uint key (total order, incl. negatives)
__device__ __forceinline__ unsigned sortable(float v) {
    unsigned b = __float_as_uint(v);
    return b ^ (unsigned)(((int)b >> 31) | 0x80000000);
}

__global__ __launch_bounds__(128, 1)
void controller_kernel(const float* __restrict__ w_ih,
                       const float* __restrict__ w_hh,
                       const float* __restrict__ b_ih,
                       const float* __restrict__ b_hh,
                       const float* __restrict__ g_emb,
                       const float* __restrict__ emb_kernel,
                       const float* __restrict__ emb_down,
                       const float* __restrict__ emb_up,
                       const float* __restrict__ w_kernel,
                       const float* __restrict__ w_down,
                       const float* __restrict__ w_up,
                       const float* __restrict__ noise,
                       float* __restrict__ out,
                       int out_size) {
    // Wx[e][r] = (w_ih @ emb_e)[r] + b_ih[r] + b_hh[r]
    // e: 0 = g_emb, 1..8 = kernel, 9..11 = down, 12..14 = up
    __shared__ float Wx[15][128];
    __shared__ __align__(16) float embsh[15][32];
    __shared__ __align__(16) float hsh[4][32];   // per-warp private h
    __shared__ float act[2][128];                // double-buffered activations
    __shared__ float gsh[160];                   // gumbels (mask folded in)
    __shared__ __align__(16) float projsh[3][8 * 36];
    __shared__ float logsh[T_STEPS][8];
    __shared__ int   ssh[T_STEPS];

    const int tid = threadIdx.x;
    const int wid = tid >> 5;
    const int j   = tid & 31;
    const int a   = j & 7;
    const int seg = j >> 3;
    const int sb  = seg * 8;

    // ---- load W rows for gate-row `tid` ----
    float wr[32];   // w_hh row (loop)
    float wi[32];   // w_ih row (init only)
    {
        const float4* wi4 = (const float4*)w_ih;
        const float4* wh4 = (const float4*)w_hh;
#pragma unroll
        for (int i = 0; i < 8; ++i) {
            float4 b = wh4[tid * 8 + i];
            wr[4 * i + 0] = b.x; wr[4 * i + 1] = b.y;
            wr[4 * i + 2] = b.z; wr[4 * i + 3] = b.w;
            float4 q = wi4[tid * 8 + i];
            wi[4 * i + 0] = q.x; wi[4 * i + 1] = q.y;
            wi[4 * i + 2] = q.z; wi[4 * i + 3] = q.w;
        }
    }
    const float bias = b_ih[tid] + b_hh[tid];

    // ---- stage embeddings / proj tables / gumbels ----
    for (int i = tid; i < 3 * 8 * 36; i += 128)
        ((float*)projsh)[i] = 0.0f;
    if (tid < 32) embsh[0][tid] = g_emb[tid];
    for (int i = tid; i < 8 * 32; i += 128)
        embsh[1 + (i >> 5)][i & 31] = emb_kernel[i];
    for (int i = tid; i < 3 * 32; i += 128) {
        embsh[9  + (i >> 5)][i & 31] = emb_down[i];
        embsh[12 + (i >> 5)][i & 31] = emb_up[i];
    }
    // gumbels with class mask folded in: invalid (t>=14, a>=3) -> -3e9
    for (int i = tid; i < T_STEPS * 8; i += 128) {
        const int tt = i >> 3, aa = i & 7;
        const bool valid = (tt < 14) || (aa < 3);
        float u = noise[i];
        gsh[i] = valid ? -logf(-logf(u * (1.0f - 1e-6f) + 1e-7f)) : -3e9f;
    }
    ((float*)hsh)[tid] = 0.0f;
    __syncthreads();

    for (int i = tid; i < 8 * 32; i += 128)
        projsh[0][(i >> 5) * 36 + (i & 31)] = w_kernel[i];
    for (int i = tid; i < 3 * 32; i += 128) {
        projsh[1][(i >> 5) * 36 + (i & 31)] = w_down[i];
        projsh[2][(i >> 5) * 36 + (i & 31)] = w_up[i];
    }

    // ---- precompute Wx (ILP across the 15 matvecs) ----
#pragma unroll 5
    for (int e = 0; e < 15; ++e) {
        const float4* em4 = (const float4*)embsh[e];
        float a0 = bias, a1 = 0.0f, a2 = 0.0f, a3 = 0.0f;
#pragma unroll
        for (int i = 0; i < 8; ++i) {
            float4 v = em4[i];
            a0 = fmaf(wi[4 * i + 0], v.x, a0);
            a1 = fmaf(wi[4 * i + 1], v.y, a1);
            a2 = fmaf(wi[4 * i + 2], v.z, a2);
            a3 = fmaf(wi[4 * i + 3], v.w, a3);
        }
        Wx[e][tid] = (a0 + a1) + (a2 + a3);
    }
    __syncthreads();

    const bool is_sig = (tid < 64) || (tid >= 96);   // warp-uniform

    // phase-0 state: proj regs, candidate Wx prefetch
    float4 p0v, p1v;
    {
        const float* pr = &projsh[0][a * 36 + sb];
        p0v = *(const float4*)(pr);
        p1v = *(const float4*)(pr + 4);
    }
    float w0 = Wx[1][tid], w1 = Wx[2][tid], w2 = Wx[3][tid], w3 = Wx[4][tid];
    float w4 = Wx[5][tid], w5 = Wx[6][tid], w6 = Wx[7][tid], w7 = Wx[8][tid];

    // act for t=0: h0 = 0 -> gacc = Wx[0]
    {
        const float g0 = Wx[0][tid];
        act[0][tid] = is_sig ? sigapx(g0) : tanhapx(g0);
    }
    float c = 0.0f;
    __syncthreads();

#pragma unroll 2
    for (int t = 0; t < T_STEPS; ++t) {
        // phase change (affects logits of this step AND emb candidates)
        if (t == 14 || t == 17) {
            const int phi = (t == 14) ? 1 : 2;
            const int eb  = (t == 14) ? 9 : 12;
            const float* pr = &projsh[phi][a * 36 + sb];
            p0v = *(const float4*)(pr);
            p1v = *(const float4*)(pr + 4);
            w0 = Wx[eb][tid]; w1 = Wx[eb + 1][tid]; w2 = Wx[eb + 2][tid];
            // w3..w7 stale but unreachable (invalid classes masked via gsh)
        }
        const int tb = t & 1;
        const float gl = gsh[t * 8 + a];

        // ---- LSTM cell from activations ----
        const float ai = act[tb][j];
        const float af = act[tb][j + 32];
        const float ag = act[tb][j + 64];
        const float ao = act[tb][j + 96];
        c = fmaf(af, c, ai * ag);
        const float h = ao * tanhapx(c);

        // ---- logits: gather 8 h values via shfl, dot with proj regs ----
        float l0 = p0v.x * __shfl_sync(FULL, h, sb + 0);
        float l1 = p0v.y * __shfl_sync(FULL, h, sb + 1);
        l0 = fmaf(p0v.z, __shfl_sync(FULL, h, sb + 2), l0);
        l1 = fmaf(p0v.w, __shfl_sync(FULL, h, sb + 3), l1);
        l0 = fmaf(p1v.x, __shfl_sync(FULL, h, sb + 4), l0);
        l1 = fmaf(p1v.y, __shfl_sync(FULL, h, sb + 5), l1);
        l0 = fmaf(p1v.z, __shfl_sync(FULL, h, sb + 6), l0);
        l1 = fmaf(p1v.w, __shfl_sync(FULL, h, sb + 7), l1);
        float part = l0 + l1;
        part += __shfl_xor_sync(FULL, part, 8);
        part += __shfl_xor_sync(FULL, part, 16);
        // raw logit; invalid classes handled via gl = -3e9 for sampling,
        // and by the k<nvalid loop in the deferred stats.

        // ---- publish h; next-step w_hh @ h matvec (overlaps argmax) ----
        hsh[wid][j] = h;
        __syncwarp();
        float a0 = 0.0f, a1 = 0.0f, a2 = 0.0f, a3 = 0.0f;
        const float4* h4 = (const float4*)hsh[wid];
#pragma unroll
        for (int i = 0; i < 8; ++i) {
            float4 v = h4[i];
            a0 = fmaf(wr[4 * i + 0], v.x, a0);
            a1 = fmaf(wr[4 * i + 1], v.y, a1);
            a2 = fmaf(wr[4 * i + 2], v.z, a2);
            a3 = fmaf(wr[4 * i + 3], v.w, a3);
        }
        const float ghh = (a0 + a1) + (a2 + a3);

        // ---- Gumbel-argmax: index in key low bits, one redux ----
        // top 29 bits: value order; low 3 bits: 7-a (ties -> lowest class)
        const unsigned key = (sortable(part + gl) & ~7u) | (unsigned)(7 - a);
        unsigned km;
        asm("redux.sync.max.u32 %0, %1, 0xffffffff;" : "=r"(km) : "r"(key));
        const int s = 7 - (int)(km & 7u);

        // stash for deferred stats (warp 0)
        if (tid < 8) {
            logsh[t][a] = part;
            if (tid == 0) ssh[t] = s;
        }

        // ---- select sampled Wx candidate (3-level SEL tree) ----
        if (t < T_STEPS - 1) {
            const float t01 = (s & 1) ? w1 : w0;
            const float t23 = (s & 1) ? w3 : w2;
            const float t45 = (s & 1) ? w5 : w4;
            const float t67 = (s & 1) ? w7 : w6;
            const float t03 = (s & 2) ? t23 : t01;
            const float t47 = (s & 2) ? t67 : t45;
            const float wx  = (s & 4) ? t47 : t03;
            const float gacc = ghh + wx;
            act[tb ^ 1][tid] = is_sig ? sigapx(gacc) : tanhapx(gacc);
        }
        __syncthreads();
    }

    // ---- deferred stats: 20 softmaxes in parallel (warp 0) ----
    if (wid == 0) {
        __syncwarp();
        float lp = 0.0f, ent = 0.0f;
        if (j < T_STEPS) {
            const int s = ssh[j];
            const int nvalid = (j < 14) ? 8 : 3;
            float se = 0.0f, ss1 = 0.0f;
#pragma unroll
            for (int k = 0; k < 8; ++k) {
                if (k < nvalid) {
                    const float l = logsh[j][k];
                    const float e = __expf(l);
                    se  += e;
                    ss1 += e * l;
                }
            }
            const float lse = __logf(se);
            lp  = logsh[j][s] - lse;
            ent = lse - __fdividef(ss1, se);
            out[2 + j] = (float)s;
        }
#pragma unroll
        for (int o = 16; o > 0; o >>= 1) {
            lp  += __shfl_xor_sync(FULL, lp,  o);
            ent += __shfl_xor_sync(FULL, ent, o);
        }
        if (j == 0) {
            out[0] = lp;
            out[1] = ent;
        }
    }
}

extern "C" void kernel_launch(void* const* d_in, const int* in_sizes, int n_in,
                              void* d_out, int out_size) {
    const float* w_ih       = (const float*)d_in[0];
    const float* w_hh       = (const float*)d_in[1];
    const float* b_ih       = (const float*)d_in[2];
    const float* b_hh       = (const float*)d_in[3];
    const float* g_emb      = (const float*)d_in[4];
    const float* emb_kernel = (const float*)d_in[5];
    const float* emb_down   = (const float*)d_in[6];
    const float* emb_up     = (const float*)d_in[7];
    const float* w_kernel   = (const float*)d_in[8];
    const float* w_down     = (const float*)d_in[9];
    const float* w_up       = (const float*)d_in[10];
    const float* noise      = (const float*)d_in[11];
    float* out = (float*)d_out;

    controller_kernel<<<1, 128>>>(w_ih, w_hh, b_ih, b_hh, g_emb,
                                  emb_kernel, emb_down, emb_up,
                                  w_kernel, w_down, w_up, noise,
                                  out, out_size);
}

// round 11
// speedup vs baseline: 1.5000x; 1.0175x over previous
#include <cuda_runtime.h>
#include <math.h>

#define T_STEPS 20
#define FULL 0xffffffffu

__device__ __forceinline__ float tanhapx(float x) {
    float y;
    asm("tanh.approx.f32 %0, %1;" : "=f"(y) : "f"(x));
    return y;
}
__device__ __forceinline__ float sigapx(float x) {
    return fmaf(0.5f, tanhapx(0.5f * x), 0.5f);
}

__global__ __launch_bounds__(128, 1)
void controller_kernel(const float* __restrict__ w_ih,
                       const float* __restrict__ w_hh,
                       const float* __restrict__ b_ih,
                       const float* __restrict__ b_hh,
                       const float* __restrict__ g_emb,
                       const float* __restrict__ emb_kernel,
                       const float* __restrict__ emb_down,
                       const float* __restrict__ emb_up,
                       const float* __restrict__ w_kernel,
                       const float* __restrict__ w_down,
                       const float* __restrict__ w_up,
                       const float* __restrict__ noise,
                       float* __restrict__ out,
                       int out_size) {
    // Wx[e][r] = (w_ih @ emb_e)[r] + b_ih[r] + b_hh[r]
    // e: 0 = g_emb, 1..8 = kernel, 9..11 = down, 12..14 = up
    __shared__ float Wx[15][128];
    __shared__ __align__(16) float embsh[15][32];
    __shared__ __align__(16) float hsh[4][32];   // per-warp private h
    __shared__ float act[2][128];                // double-buffered activations
    __shared__ float gsh[160];                   // gumbels (mask+bias folded)
    __shared__ __align__(16) float projsh[3][8 * 36];
    __shared__ float logsh[T_STEPS][8];
    __shared__ int   ssh[T_STEPS];

    const int tid = threadIdx.x;
    const int wid = tid >> 5;
    const int j   = tid & 31;
    const int a   = j & 7;
    const int seg = j >> 3;
    const int sb  = seg * 8;

    // ---- load W rows for gate-row `tid` ----
    float wr[32];   // w_hh row (loop)
    float wi[32];   // w_ih row (init only)
    {
        const float4* wi4 = (const float4*)w_ih;
        const float4* wh4 = (const float4*)w_hh;
#pragma unroll
        for (int i = 0; i < 8; ++i) {
            float4 b = wh4[tid * 8 + i];
            wr[4 * i + 0] = b.x; wr[4 * i + 1] = b.y;
            wr[4 * i + 2] = b.z; wr[4 * i + 3] = b.w;
            float4 q = wi4[tid * 8 + i];
            wi[4 * i + 0] = q.x; wi[4 * i + 1] = q.y;
            wi[4 * i + 2] = q.z; wi[4 * i + 3] = q.w;
        }
    }
    const float bias = b_ih[tid] + b_hh[tid];

    // ---- stage embeddings / proj tables / gumbels ----
    for (int i = tid; i < 3 * 8 * 36; i += 128)
        ((float*)projsh)[i] = 0.0f;
    if (tid < 32) embsh[0][tid] = g_emb[tid];
    for (int i = tid; i < 8 * 32; i += 128)
        embsh[1 + (i >> 5)][i & 31] = emb_kernel[i];
    for (int i = tid; i < 3 * 32; i += 128) {
        embsh[9  + (i >> 5)][i & 31] = emb_down[i];
        embsh[12 + (i >> 5)][i & 31] = emb_up[i];
    }
    // gumbels, mask + positivity bias folded in:
    //  valid:   gumbel + 32  -> v = part + gl in [~26, ~50]  (always > 0)
    //  invalid: 8            -> v = part + 8  in [4.7, 11.3] (< valid min)
    // positive floats compare like their uint bits -> no sortable() needed
    for (int i = tid; i < T_STEPS * 8; i += 128) {
        const int tt = i >> 3, aa = i & 7;
        const bool valid = (tt < 14) || (aa < 3);
        float u = noise[i];
        gsh[i] = valid ? (32.0f - logf(-logf(u * (1.0f - 1e-6f) + 1e-7f)))
                       : 8.0f;
    }
    ((float*)hsh)[tid] = 0.0f;
    __syncthreads();

    for (int i = tid; i < 8 * 32; i += 128)
        projsh[0][(i >> 5) * 36 + (i & 31)] = w_kernel[i];
    for (int i = tid; i < 3 * 32; i += 128) {
        projsh[1][(i >> 5) * 36 + (i & 31)] = w_down[i];
        projsh[2][(i >> 5) * 36 + (i & 31)] = w_up[i];
    }

    // ---- precompute Wx (ILP across the 15 matvecs) ----
#pragma unroll 5
    for (int e = 0; e < 15; ++e) {
        const float4* em4 = (const float4*)embsh[e];
        float a0 = bias, a1 = 0.0f, a2 = 0.0f, a3 = 0.0f;
#pragma unroll
        for (int i = 0; i < 8; ++i) {
            float4 v = em4[i];
            a0 = fmaf(wi[4 * i + 0], v.x, a0);
            a1 = fmaf(wi[4 * i + 1], v.y, a1);
            a2 = fmaf(wi[4 * i + 2], v.z, a2);
            a3 = fmaf(wi[4 * i + 3], v.w, a3);
        }
        Wx[e][tid] = (a0 + a1) + (a2 + a3);
    }
    __syncthreads();

    const bool is_sig = (tid < 64) || (tid >= 96);   // warp-uniform

    // phase-0 state: proj regs, candidate Wx prefetch
    float4 p0v, p1v;
    {
        const float* pr = &projsh[0][a * 36 + sb];
        p0v = *(const float4*)(pr);
        p1v = *(const float4*)(pr + 4);
    }
    float w0 = Wx[1][tid], w1 = Wx[2][tid], w2 = Wx[3][tid], w3 = Wx[4][tid];
    float w4 = Wx[5][tid], w5 = Wx[6][tid], w6 = Wx[7][tid], w7 = Wx[8][tid];

    // act for t=0: h0 = 0 -> gacc = Wx[0]
    {
        const float g0 = Wx[0][tid];
        act[0][tid] = is_sig ? sigapx(g0) : tanhapx(g0);
    }
    float c = 0.0f;
    __syncthreads();

#pragma unroll
    for (int t = 0; t < T_STEPS; ++t) {
        // phase change (affects logits of this step AND emb candidates)
        if (t == 14 || t == 17) {
            const int phi = (t == 14) ? 1 : 2;
            const int eb  = (t == 14) ? 9 : 12;
            const float* pr = &projsh[phi][a * 36 + sb];
            p0v = *(const float4*)(pr);
            p1v = *(const float4*)(pr + 4);
            w0 = Wx[eb][tid]; w1 = Wx[eb + 1][tid]; w2 = Wx[eb + 2][tid];
            // w3..w7 stale but unreachable (invalid classes masked via gsh)
        }
        const int tb = t & 1;                 // constant after full unroll
        const float gl = gsh[t * 8 + a];

        // ---- LSTM cell from activations ----
        const float ai = act[tb][j];
        const float af = act[tb][j + 32];
        const float ag = act[tb][j + 64];
        const float ao = act[tb][j + 96];
        c = fmaf(af, c, ai * ag);
        const float h = ao * tanhapx(c);

        // ---- logits: gather 8 h values via shfl, dot with proj regs ----
        float l0 = p0v.x * __shfl_sync(FULL, h, sb + 0);
        float l1 = p0v.y * __shfl_sync(FULL, h, sb + 1);
        l0 = fmaf(p0v.z, __shfl_sync(FULL, h, sb + 2), l0);
        l1 = fmaf(p0v.w, __shfl_sync(FULL, h, sb + 3), l1);
        l0 = fmaf(p1v.x, __shfl_sync(FULL, h, sb + 4), l0);
        l1 = fmaf(p1v.y, __shfl_sync(FULL, h, sb + 5), l1);
        l0 = fmaf(p1v.z, __shfl_sync(FULL, h, sb + 6), l0);
        l1 = fmaf(p1v.w, __shfl_sync(FULL, h, sb + 7), l1);
        float part = l0 + l1;
        part += __shfl_xor_sync(FULL, part, 8);
        part += __shfl_xor_sync(FULL, part, 16);
        // raw logit; masking handled via gsh bias + stats nvalid loop

        // ---- publish h; next-step w_hh @ h matvec (overlaps argmax) ----
        hsh[wid][j] = h;
        __syncwarp();
        float a0 = 0.0f, a1 = 0.0f, a2 = 0.0f, a3 = 0.0f;
        const float4* h4 = (const float4*)hsh[wid];
#pragma unroll
        for (int i = 0; i < 8; ++i) {
            float4 v = h4[i];
            a0 = fmaf(wr[4 * i + 0], v.x, a0);
            a1 = fmaf(wr[4 * i + 1], v.y, a1);
            a2 = fmaf(wr[4 * i + 2], v.z, a2);
            a3 = fmaf(wr[4 * i + 3], v.w, a3);
        }
        const float ghh = (a0 + a1) + (a2 + a3);

        // ---- Gumbel-argmax: positive v -> raw uint bits are ordered ----
        // low 3 bits carry 7-a (ties -> lowest class); km bits = ~s bits
        const unsigned key = (__float_as_uint(part + gl) & ~7u)
                           | (unsigned)(7 - a);
        unsigned km;
        asm("redux.sync.max.u32 %0, %1, 0xffffffff;" : "=r"(km) : "r"(key));

        // ---- select sampled Wx via km bits directly (km = ...|7-s) ----
        if (t < T_STEPS - 1) {
            const float t01 = (km & 1) ? w0 : w1;
            const float t23 = (km & 1) ? w2 : w3;
            const float t45 = (km & 1) ? w4 : w5;
            const float t67 = (km & 1) ? w6 : w7;
            const float t03 = (km & 2) ? t01 : t23;
            const float t47 = (km & 2) ? t45 : t67;
            const float wx  = (km & 4) ? t03 : t47;
            const float gacc = ghh + wx;
            act[tb ^ 1][tid] = is_sig ? sigapx(gacc) : tanhapx(gacc);
        }
        __syncthreads();

        // ---- stash AFTER barrier: warp-0 private, read only by warp 0 ----
        if (tid < 8) {
            logsh[t][a] = part;
            if (tid == 0) ssh[t] = (int)((km & 7u) ^ 7u);
        }
    }

    // ---- deferred stats: 20 softmaxes in parallel (warp 0) ----
    if (wid == 0) {
        __syncwarp();
        float lp = 0.0f, ent = 0.0f;
        if (j < T_STEPS) {
            const int s = ssh[j];
            const int nvalid = (j < 14) ? 8 : 3;
            float se = 0.0f, ss1 = 0.0f;
#pragma unroll
            for (int k = 0; k < 8; ++k) {
                if (k < nvalid) {
                    const float l = logsh[j][k];
                    const float e = __expf(l);
                    se  += e;
                    ss1 += e * l;
                }
            }
            const float lse = __logf(se);
            lp  = logsh[j][s] - lse;
            ent = lse - __fdividef(ss1, se);
            out[2 + j] = (float)s;
        }
#pragma unroll
        for (int o = 16; o > 0; o >>= 1) {
            lp  += __shfl_xor_sync(FULL, lp,  o);
            ent += __shfl_xor_sync(FULL, ent, o);
        }
        if (j == 0) {
            out[0] = lp;
            out[1] = ent;
        }
    }
}

extern "C" void kernel_launch(void* const* d_in, const int* in_sizes, int n_in,
                              void* d_out, int out_size) {
    const float* w_ih       = (const float*)d_in[0];
    const float* w_hh       = (const float*)d_in[1];
    const float* b_ih       = (const float*)d_in[2];
    const float* b_hh       = (const float*)d_in[3];
    const float* g_emb      = (const float*)d_in[4];
    const float* emb_kernel = (const float*)d_in[5];
    const float* emb_down   = (const float*)d_in[6];
    const float* emb_up     = (const float*)d_in[7];
    const float* w_kernel   = (const float*)d_in[8];
    const float* w_down     = (const float*)d_in[9];
    const float* w_up       = (const float*)d_in[10];
    const float* noise      = (const float*)d_in[11];
    float* out = (float*)d_out;

    controller_kernel<<<1, 128>>>(w_ih, w_hh, b_ih, b_hh, g_emb,
                                  emb_kernel, emb_down, emb_up,
                                  w_kernel, w_down, w_up, noise,
                                  out, out_size);
}

// round 12
// speedup vs baseline: 1.5038x; 1.0025x over previous
#include <cuda_runtime.h>
#include <math.h>

#define T_STEPS 20
#define FULL 0xffffffffu

__device__ __forceinline__ float tanhapx(float x) {
    float y;
    asm("tanh.approx.f32 %0, %1;" : "=f"(y) : "f"(x));
    return y;
}
__device__ __forceinline__ float sigapx(float x) {
    return fmaf(0.5f, tanhapx(0.5f * x), 0.5f);
}

__global__ __launch_bounds__(128, 1)
void controller_kernel(const float* __restrict__ w_ih,
                       const float* __restrict__ w_hh,
                       const float* __restrict__ b_ih,
                       const float* __restrict__ b_hh,
                       const float* __restrict__ g_emb,
                       const float* __restrict__ emb_kernel,
                       const float* __restrict__ emb_down,
                       const float* __restrict__ emb_up,
                       const float* __restrict__ w_kernel,
                       const float* __restrict__ w_down,
                       const float* __restrict__ w_up,
                       const float* __restrict__ noise,
                       float* __restrict__ out,
                       int out_size) {
    // Wx[e][r] = (w_ih @ emb_e)[r] + b_ih[r] + b_hh[r]
    // e: 0 = g_emb, 1..8 = kernel, 9..11 = down, 12..14 = up
    __shared__ float Wx[15][128];
    __shared__ __align__(16) float embsh[15][32];
    __shared__ __align__(16) float hsh[2][32];   // double-buffered h
    __shared__ float gsh[160];                   // gumbels (mask+bias folded)
    __shared__ __align__(16) float projsh[3][8 * 36];
    __shared__ float logsh[T_STEPS][8];
    __shared__ int   ssh[T_STEPS];

    const int tid = threadIdx.x;

    // ================= init: all 128 threads =================
    {
        // w_ih row `tid` for the Wx precompute
        float wi[32];
        const float4* wi4 = (const float4*)w_ih;
#pragma unroll
        for (int i = 0; i < 8; ++i) {
            float4 q = wi4[tid * 8 + i];
            wi[4 * i + 0] = q.x; wi[4 * i + 1] = q.y;
            wi[4 * i + 2] = q.z; wi[4 * i + 3] = q.w;
        }
        const float bias = b_ih[tid] + b_hh[tid];

        for (int i = tid; i < 3 * 8 * 36; i += 128)
            ((float*)projsh)[i] = 0.0f;
        if (tid < 32) embsh[0][tid] = g_emb[tid];
        for (int i = tid; i < 8 * 32; i += 128)
            embsh[1 + (i >> 5)][i & 31] = emb_kernel[i];
        for (int i = tid; i < 3 * 32; i += 128) {
            embsh[9  + (i >> 5)][i & 31] = emb_down[i];
            embsh[12 + (i >> 5)][i & 31] = emb_up[i];
        }
        // gumbels, mask + positivity bias folded in:
        //  valid:   gumbel + 32 -> v in [~26, ~50]  (> 0)
        //  invalid: 8           -> v in [4.7, 11.3] (< valid min)
        for (int i = tid; i < T_STEPS * 8; i += 128) {
            const int tt = i >> 3, aa = i & 7;
            const bool valid = (tt < 14) || (aa < 3);
            float u = noise[i];
            gsh[i] = valid ? (32.0f - logf(-logf(u * (1.0f - 1e-6f) + 1e-7f)))
                           : 8.0f;
        }
        __syncthreads();

        for (int i = tid; i < 8 * 32; i += 128)
            projsh[0][(i >> 5) * 36 + (i & 31)] = w_kernel[i];
        for (int i = tid; i < 3 * 32; i += 128) {
            projsh[1][(i >> 5) * 36 + (i & 31)] = w_down[i];
            projsh[2][(i >> 5) * 36 + (i & 31)] = w_up[i];
        }

#pragma unroll 5
        for (int e = 0; e < 15; ++e) {
            const float4* em4 = (const float4*)embsh[e];
            float a0 = bias, a1 = 0.0f, a2 = 0.0f, a3 = 0.0f;
#pragma unroll
            for (int i = 0; i < 8; ++i) {
                float4 v = em4[i];
                a0 = fmaf(wi[4 * i + 0], v.x, a0);
                a1 = fmaf(wi[4 * i + 1], v.y, a1);
                a2 = fmaf(wi[4 * i + 2], v.z, a2);
                a3 = fmaf(wi[4 * i + 3], v.w, a3);
            }
            Wx[e][tid] = (a0 + a1) + (a2 + a3);
        }
    }
    __syncthreads();

    if (tid >= 32) return;   // warps 1-3 done; no more block barriers

    // ================= single-warp recurrence: lane j = state j ===========
    const int j   = tid;
    const int a   = j & 7;
    const int sb  = (j >> 3) * 8;

    // w_hh rows j (i-gate), j+32 (f), j+64 (g), j+96 (o) into registers
    float wgi[32], wgf[32], wgg[32], wgo[32];
    {
        const float4* wh4 = (const float4*)w_hh;
#pragma unroll
        for (int i = 0; i < 8; ++i) {
            float4 v;
            v = wh4[j * 8 + i];
            wgi[4 * i + 0] = v.x; wgi[4 * i + 1] = v.y;
            wgi[4 * i + 2] = v.z; wgi[4 * i + 3] = v.w;
            v = wh4[(j + 32) * 8 + i];
            wgf[4 * i + 0] = v.x; wgf[4 * i + 1] = v.y;
            wgf[4 * i + 2] = v.z; wgf[4 * i + 3] = v.w;
            v = wh4[(j + 64) * 8 + i];
            wgg[4 * i + 0] = v.x; wgg[4 * i + 1] = v.y;
            wgg[4 * i + 2] = v.z; wgg[4 * i + 3] = v.w;
            v = wh4[(j + 96) * 8 + i];
            wgo[4 * i + 0] = v.x; wgo[4 * i + 1] = v.y;
            wgo[4 * i + 2] = v.z; wgo[4 * i + 3] = v.w;
        }
    }

    // phase-0 proj regs
    float4 p0v, p1v;
    {
        const float* pr = &projsh[0][a * 36 + sb];
        p0v = *(const float4*)(pr);
        p1v = *(const float4*)(pr + 4);
    }
    int ebase = 1;

    // prologue: h0 = 0, c0 = 0 -> gates = Wx[0]
    float c, h;
    {
        const float ai = sigapx(Wx[0][j]);
        const float af = sigapx(Wx[0][j + 32]);   (void)af;
        const float ag = tanhapx(Wx[0][j + 64]);
        const float ao = sigapx(Wx[0][j + 96]);
        c = ai * ag;                    // af * c0 = 0
        h = ao * tanhapx(c);
    }

#pragma unroll 2
    for (int t = 0; t < T_STEPS; ++t) {
        if (t == 14 || t == 17) {
            const int phi = (t == 14) ? 1 : 2;
            ebase = (t == 14) ? 9 : 12;
            const float* pr = &projsh[phi][a * 36 + sb];
            p0v = *(const float4*)(pr);
            p1v = *(const float4*)(pr + 4);
        }
        const int p = t & 1;
        const float gl = gsh[t * 8 + a];

        // publish h for this step (double buffer -> 1 syncwarp suffices)
        hsh[p][j] = h;
        __syncwarp();

        // ---- logits: lane = (class a, segment sb) ----
        const float4 q0 = *(const float4*)&hsh[p][sb];
        const float4 q1 = *(const float4*)&hsh[p][sb + 4];
        float l0 = p0v.x * q0.x + p0v.y * q0.y + p0v.z * q0.z + p0v.w * q0.w;
        float l1 = p1v.x * q1.x + p1v.y * q1.y + p1v.z * q1.z + p1v.w * q1.w;
        float part = l0 + l1;
        part += __shfl_xor_sync(FULL, part, 8);
        part += __shfl_xor_sync(FULL, part, 16);

        // ---- 4-gate matvec for state j (fills redux/shfl latency) ----
        float A0 = 0.f, A1 = 0.f, B0 = 0.f, B1 = 0.f;
        float C0 = 0.f, C1 = 0.f, D0 = 0.f, D1 = 0.f;
        const float4* h4 = (const float4*)hsh[p];
#pragma unroll
        for (int i = 0; i < 8; ++i) {
            const float4 v = h4[i];
            A0 = fmaf(wgi[4 * i + 0], v.x, A0);
            A1 = fmaf(wgi[4 * i + 1], v.y, A1);
            A0 = fmaf(wgi[4 * i + 2], v.z, A0);
            A1 = fmaf(wgi[4 * i + 3], v.w, A1);
            B0 = fmaf(wgf[4 * i + 0], v.x, B0);
            B1 = fmaf(wgf[4 * i + 1], v.y, B1);
            B0 = fmaf(wgf[4 * i + 2], v.z, B0);
            B1 = fmaf(wgf[4 * i + 3], v.w, B1);
            C0 = fmaf(wgg[4 * i + 0], v.x, C0);
            C1 = fmaf(wgg[4 * i + 1], v.y, C1);
            C0 = fmaf(wgg[4 * i + 2], v.z, C0);
            C1 = fmaf(wgg[4 * i + 3], v.w, C1);
            D0 = fmaf(wgo[4 * i + 0], v.x, D0);
            D1 = fmaf(wgo[4 * i + 1], v.y, D1);
            D0 = fmaf(wgo[4 * i + 2], v.z, D0);
            D1 = fmaf(wgo[4 * i + 3], v.w, D1);
        }
        const float ghi = A0 + A1, ghf = B0 + B1;
        const float ghg = C0 + C1, gho = D0 + D1;

        // ---- Gumbel-argmax: positive v -> uint bits ordered ----
        const unsigned key = (__float_as_uint(part + gl) & ~7u)
                           | (unsigned)(7 - a);
        unsigned km;
        asm("redux.sync.max.u32 %0, %1, 0xffffffff;" : "=r"(km) : "r"(key));
        const int s = (int)((km & 7u) ^ 7u);

        // stash stats (lanes 0-7 hold seg-0 partials = full logits)
        if (j < 8) {
            logsh[t][j] = part;
            if (j == 0) ssh[t] = s;
        }

        // ---- next-state update: Wx lookup by sampled class ----
        if (t < T_STEPS - 1) {
            const float* wxr = Wx[ebase + s];
            const float ai = sigapx(ghi + wxr[j]);
            const float af = sigapx(ghf + wxr[j + 32]);
            const float ag = tanhapx(ghg + wxr[j + 64]);
            const float ao = sigapx(gho + wxr[j + 96]);
            c = fmaf(af, c, ai * ag);
            h = ao * tanhapx(c);
        }
    }

    // ================= deferred stats (still warp 0) =================
    __syncwarp();
    float lp = 0.0f, ent = 0.0f;
    if (j < T_STEPS) {
        const int s = ssh[j];
        const int nvalid = (j < 14) ? 8 : 3;
        float se = 0.0f, ss1 = 0.0f;
#pragma unroll
        for (int k = 0; k < 8; ++k) {
            if (k < nvalid) {
                const float l = logsh[j][k];
                const float e = __expf(l);
                se  += e;
                ss1 += e * l;
            }
        }
        const float lse = __logf(se);
        lp  = logsh[j][s] - lse;
        ent = lse - __fdividef(ss1, se);
        out[2 + j] = (float)s;
    }
#pragma unroll
    for (int o = 16; o > 0; o >>= 1) {
        lp  += __shfl_xor_sync(FULL, lp,  o);
        ent += __shfl_xor_sync(FULL, ent, o);
    }
    if (j == 0) {
        out[0] = lp;
        out[1] = ent;
    }
}

extern "C" void kernel_launch(void* const* d_in, const int* in_sizes, int n_in,
                              void* d_out, int out_size) {
    const float* w_ih       = (const float*)d_in[0];
    const float* w_hh       = (const float*)d_in[1];
    const float* b_ih       = (const float*)d_in[2];
    const float* b_hh       = (const float*)d_in[3];
    const float* g_emb      = (const float*)d_in[4];
    const float* emb_kernel = (const float*)d_in[5];
    const float* emb_down   = (const float*)d_in[6];
    const float* emb_up     = (const float*)d_in[7];
    const float* w_kernel   = (const float*)d_in[8];
    const float* w_down     = (const float*)d_in[9];
    const float* w_up       = (const float*)d_in[10];
    const float* noise      = (const float*)d_in[11];
    float* out = (float*)d_out;

    controller_kernel<<<1, 128>>>(w_ih, w_hh, b_ih, b_hh, g_emb,
                                  emb_kernel, emb_down, emb_up,
                                  w_kernel, w_down, w_up, noise,
                                  out, out_size);
}